// round 11
// baseline (speedup 1.0000x reference)
#include <cuda_runtime.h>

#define FULL 0xffffffffu

// theta-derived tables (sample-independent). Amp index I: bit q = qubit q.
// qsim layout: I = (g<<4)|j, g = lane&15 (qubits 4..7), j = reg idx (qubits 0..3).
// Tables transposed [j*16+g] -> coalesced lane loads.
// Tangent-form gates: g_ryt[k] = tan(th_k/2); product of all 16 cos(th_k/2)
// folded into g_d0t, so each gate costs 1 FMA/element.
__device__ float g_ryt[16];
__device__ __align__(16) float2 g_d0t[256];   // norm * (cos phi, sin phi)
__device__ __align__(16) float2 g_d1t[256];   // (cos psi, sin psi)

__global__ void precompute_kernel(const float* __restrict__ theta) {
    int I = threadIdx.x;          // amp index 0..255
    if (I < 16) {
        int layer = I >> 3, q = I & 7;
        float th = theta[layer * 24 + q * 3 + 1];
        g_ryt[I] = tanf(0.5f * th);
    }
    // global normalization: product of cos(th/2) over all 16 RY gates
    float norm = 1.0f;
    #pragma unroll
    for (int k = 0; k < 16; k++) {
        int layer = k >> 3, q = k & 7;
        norm *= cosf(0.5f * theta[layer * 24 + q * 3 + 1]);
    }

    int tslot = (I & 15) * 16 + (I >> 4);   // transposed slot

    // D0: RZ(phi) layer 0 diag (bit=0 -> -phi/2, bit=1 -> +phi/2), scaled by norm
    float a0 = 0.0f;
    #pragma unroll
    for (int q = 0; q < 8; q++) {
        float phi = theta[q * 3 + 0];
        a0 += ((I >> q) & 1) ? 0.5f * phi : -0.5f * phi;
    }
    float sr, cr;
    sincosf(a0, &sr, &cr);
    g_d0t[tslot] = make_float2(cr * norm, sr * norm);

    // D1(K) = e^{i psi}, psi = Om0(src(K)) + Phi1(K), src(K) = K ^ ((K & 0x7F) << 1)
    int src = I ^ ((I & 0x7F) << 1);
    float a1 = 0.0f;
    #pragma unroll
    for (int q = 0; q < 8; q++) {
        float om0  = theta[q * 3 + 2];
        float phi1 = theta[24 + q * 3 + 0];
        a1 += ((src >> q) & 1) ? 0.5f * om0  : -0.5f * om0;
        a1 += ((I   >> q) & 1) ? 0.5f * phi1 : -0.5f * phi1;
    }
    sincosf(a1, &sr, &cr);
    g_d1t[tslot] = make_float2(cr, sr);
    // RZ(om) of layer 1 dropped: no effect on probabilities.
}

// In-place CNOT-perm step fused with D1: new[DST] = D1[DST] * old[SRC]@srclane
#define PERM_STEP(DST, SRC) { \
    int sl_ = slA ^ (((DST) >> 3) & 1); \
    float pr_ = __shfl_sync(FULL, ar[SRC], sl_); \
    float pi_ = __shfl_sync(FULL, ai[SRC], sl_); \
    float2 d_ = d1p[(DST) * 16]; \
    ar[DST] = d_.x * pr_ - d_.y * pi_; \
    ai[DST] = d_.x * pi_ + d_.y * pr_; }

#define PERM_LAST(DST) { \
    int sl_ = slA ^ (((DST) >> 3) & 1); \
    float pr_ = __shfl_sync(FULL, tr_, sl_); \
    float pi_ = __shfl_sync(FULL, ti_, sl_); \
    float2 d_ = d1p[(DST) * 16]; \
    ar[DST] = d_.x * pr_ - d_.y * pi_; \
    ai[DST] = d_.x * pi_ + d_.y * pr_; }

__global__ void __launch_bounds__(256, 5)
qsim_kernel(const float* __restrict__ x, float* __restrict__ out, int batch) {
    int gw   = (int)((blockIdx.x * blockDim.x + threadIdx.x) >> 5);
    int lane = threadIdx.x & 31;
    int g    = lane & 15;          // lane-qubit bits (qubits 4..7)
    int base = lane & 16;          // sample selector
    int sample = gw * 2 + (lane >> 4);
    if (gw * 2 >= batch) return;
    int sidx = sample < batch ? sample : batch - 1;

    // ---- angle encoding (register-lean) ----
    float xv = x[sidx * 8 + (g & 7)];
    xv = fminf(1.0f, fmaxf(-1.0f, xv));
    float sv, cv;
    sincospif(0.5f * xv, &sv, &cv);

    // lane factor over qubits 4..7 (g bits 0..3), folded sequentially
    float lf = 1.0f;
    #pragma unroll
    for (int q = 4; q < 8; q++) {
        float cqv = __shfl_sync(FULL, cv, base | q);
        float sqv = __shfl_sync(FULL, sv, base | q);
        lf *= ((g >> (q - 4)) & 1) ? sqv : cqv;
    }
    // c/s for reg qubits 0..3 only
    float c0 = __shfl_sync(FULL, cv, base | 0), s0 = __shfl_sync(FULL, sv, base | 0);
    float c1 = __shfl_sync(FULL, cv, base | 1), s1 = __shfl_sync(FULL, sv, base | 1);
    float c2 = __shfl_sync(FULL, cv, base | 2), s2 = __shfl_sync(FULL, sv, base | 2);
    float c3 = __shfl_sync(FULL, cv, base | 3), s3 = __shfl_sync(FULL, sv, base | 3);

    float t1a = lf * c0, t1b = lf * s0;
    float t2[4], t3[8];
    #pragma unroll
    for (int j = 0; j < 4; j++)
        t2[j] = ((j & 1) ? t1b : t1a) * ((j & 2) ? s1 : c1);
    #pragma unroll
    for (int j = 0; j < 8; j++)
        t3[j] = t2[j & 3] * ((j & 4) ? s2 : c2);

    // fold D0 (norm-scaled phi-diagonal) into the last product level
    const float2* d0p = g_d0t + g;
    float ar[16], ai[16];
    #pragma unroll
    for (int j = 0; j < 16; j++) {
        float a = t3[j & 7] * ((j & 8) ? s3 : c3);
        float2 d = d0p[j * 16];
        ar[j] = a * d.x;
        ai[j] = a * d.y;
    }

    // CNOT perm: src lane (4-bit) = g ^ ((g&7)<<1), xor'd with dst reg bit 3
    const int slA = base | (g ^ ((g & 7) << 1));
    const float2* d1p = g_d1t + g;

    // ---- two layers of tangent-form RY gates + fused perm/diagonal ----
    #pragma unroll
    for (int layer = 0; layer < 2; layer++) {
        #pragma unroll
        for (int q = 0; q < 4; q++) {           // reg-qubit gates: 1 FMA/element
            float tg = g_ryt[layer * 8 + q];
            int m = 1 << q;
            #pragma unroll
            for (int j0 = 0; j0 < 16; j0++) {
                if (j0 & m) continue;
                int j1 = j0 | m;
                float b0r = ar[j0], b0i = ai[j0];
                float b1r = ar[j1], b1i = ai[j1];
                ar[j0] = fmaf(-tg, b1r, b0r);
                ai[j0] = fmaf(-tg, b1i, b0i);
                ar[j1] = fmaf( tg, b0r, b1r);
                ai[j1] = fmaf( tg, b0i, b1i);
            }
        }
        #pragma unroll
        for (int q = 4; q < 8; q++) {           // lane-qubit gates: 1 FMA/element
            float tg = g_ryt[layer * 8 + q];
            int pb = 1 << (q - 4);
            float ss = (g & pb) ? tg : -tg;
            #pragma unroll
            for (int j = 0; j < 16; j++) {
                float pr = __shfl_xor_sync(FULL, ar[j], pb);
                float pi = __shfl_xor_sync(FULL, ai[j], pb);
                ar[j] = fmaf(ss, pr, ar[j]);
                ai[j] = fmaf(ss, pi, ai[j]);
            }
        }

        if (layer == 0) {
            // CNOT chain: new[I] = D1[I]*old[src(I)], src = I^((I&0x7F)<<1).
            // Reg part sigma(j)=j^((j&7)<<1): cycles (0)(8)(4 12)(1 3 5 15)(2 6 10 14)(7 9 11 13)
            PERM_STEP(0, 0)
            PERM_STEP(8, 8)
            { float tr_ = ar[4], ti_ = ai[4];
              PERM_STEP(4, 12) PERM_LAST(12) }
            { float tr_ = ar[1], ti_ = ai[1];
              PERM_STEP(1, 3) PERM_STEP(3, 5) PERM_STEP(5, 15) PERM_LAST(15) }
            { float tr_ = ar[2], ti_ = ai[2];
              PERM_STEP(2, 6) PERM_STEP(6, 10) PERM_STEP(10, 14) PERM_LAST(14) }
            { float tr_ = ar[7], ti_ = ai[7];
              PERM_STEP(7, 9) PERM_STEP(9, 11) PERM_STEP(11, 13) PERM_LAST(13) }
        }
        // layer 1: om-diag dropped; its CNOT chain folded into Walsh below.
    }

    // ---- measurement: e_q = sum_I (-1)^{parity(I & (2^{q+1}-1))} p_I ----
    float p[16];
    #pragma unroll
    for (int j = 0; j < 16; j++)
        p[j] = ar[j] * ar[j] + ai[j] * ai[j];

    // signed prefix-parity cascade over reg bits 0..3
    float cA[8], cB[4], cC[2];
    #pragma unroll
    for (int k = 0; k < 8; k++) cA[k] = p[2 * k] - p[2 * k + 1];
    #pragma unroll
    for (int k = 0; k < 4; k++) cB[k] = cA[2 * k] - cA[2 * k + 1];
    cC[0] = cB[0] - cB[1]; cC[1] = cB[2] - cB[3];
    float u0 = 0.0f, u1 = 0.0f;
    #pragma unroll
    for (int k = 0; k < 8; k++) u0 += cA[k];
    #pragma unroll
    for (int k = 0; k < 4; k++) u1 += cB[k];
    float u2 = cC[0] + cC[1];
    float t  = cC[0] - cC[1];     // full reg-parity term, seeds e3..e7

    // butterflies over g bits (within 16-lane sample group):
    // plain sums for u0..u2 (e0..e2); Walsh for t (e3..e7 at g=0,1,3,7,15)
    #pragma unroll
    for (int d = 1; d < 16; d <<= 1) {
        u0 += __shfl_xor_sync(FULL, u0, d);
        u1 += __shfl_xor_sync(FULL, u1, d);
        u2 += __shfl_xor_sync(FULL, u2, d);
        float pv = __shfl_xor_sync(FULL, t, d);
        t = (g & d) ? (pv - t) : (t + pv);
    }

    if (sample < batch) {
        float* o = out + sample * 8;
        if (g == 0) { o[0] = u0; o[1] = u1; o[2] = u2; o[3] = t; }
        else if ((g & (g + 1)) == 0)     // g = 1,3,7,15 -> qubits 4,5,6,7
            o[3 + __popc(g)] = t;
    }
}

extern "C" void kernel_launch(void* const* d_in, const int* in_sizes, int n_in,
                              void* d_out, int out_size) {
    const float* inputs = (const float*)d_in[0];   // [16384, 8] f32
    const float* theta  = (const float*)d_in[1];   // [2, 8, 3]  f32
    float* out = (float*)d_out;                    // [16384, 8] f32

    int batch = in_sizes[0] / 8;

    precompute_kernel<<<1, 256>>>(theta);

    int warps = (batch + 1) / 2;              // 2 samples per warp
    int threads = 256;                        // 8 warps / block
    int blocks = (warps * 32 + threads - 1) / threads;
    qsim_kernel<<<blocks, threads>>>(inputs, out, batch);
}

// round 12
// speedup vs baseline: 1.0843x; 1.0843x over previous
#include <cuda_runtime.h>

#define FULL 0xffffffffu

// In-place CNOT-perm step fused with D1: new[DST] = D1[DST] * old[SRC]@srclane
#define PERM_STEP(DST, SRC) { \
    int sl_ = slA ^ (((DST) >> 3) & 1); \
    float pr_ = __shfl_sync(FULL, ar[SRC], sl_); \
    float pi_ = __shfl_sync(FULL, ai[SRC], sl_); \
    float2 d_ = d1p[(DST) * 16]; \
    ar[DST] = d_.x * pr_ - d_.y * pi_; \
    ai[DST] = d_.x * pi_ + d_.y * pr_; }

#define PERM_LAST(DST) { \
    int sl_ = slA ^ (((DST) >> 3) & 1); \
    float pr_ = __shfl_sync(FULL, tr_, sl_); \
    float pi_ = __shfl_sync(FULL, ti_, sl_); \
    float2 d_ = d1p[(DST) * 16]; \
    ar[DST] = d_.x * pr_ - d_.y * pi_; \
    ai[DST] = d_.x * pi_ + d_.y * pr_; }

__global__ void __launch_bounds__(256)
qsim_kernel(const float* __restrict__ x, const float* __restrict__ theta,
            float* __restrict__ out, int batch) {
    // ---- per-block theta-derived tables in shared memory ----
    // Amp index I: bit q = qubit q. qsim layout: I = (g<<4)|j,
    // g = lane&15 (qubits 4..7), j = reg idx (qubits 0..3).
    // Tables transposed [j*16+g] -> conflict-free LDS.
    // Tangent-form gates: s_ryt[k] = tan(th_k/2); product of all 16 cos(th_k/2)
    // is folded into s_d0t, so each gate costs 1 FMA/element.
    __shared__ float  s_ryt[16];
    __shared__ float  s_ryc[16];
    __shared__ __align__(16) float2 s_d0t[256];   // norm * (cos phi, sin phi)
    __shared__ __align__(16) float2 s_d1t[256];   // (cos psi, sin psi)

    int tid = threadIdx.x;
    if (tid < 16) {
        int layer = tid >> 3, q = tid & 7;
        float th = 0.5f * theta[layer * 24 + q * 3 + 1];
        float sg, cg;
        sincosf(th, &sg, &cg);
        s_ryt[tid] = sg / cg;
        s_ryc[tid] = cg;
    }
    __syncthreads();

    {
        int I = tid;                           // amp index 0..255
        float norm = 1.0f;
        #pragma unroll
        for (int k = 0; k < 16; k++) norm *= s_ryc[k];

        int tslot = (I & 15) * 16 + (I >> 4);  // transposed slot

        // D0: RZ(phi) layer 0 diag (bit=0 -> -phi/2, bit=1 -> +phi/2), scaled by norm
        float a0 = 0.0f;
        #pragma unroll
        for (int q = 0; q < 8; q++) {
            float phi = theta[q * 3 + 0];
            a0 += ((I >> q) & 1) ? 0.5f * phi : -0.5f * phi;
        }
        float sr, cr;
        sincosf(a0, &sr, &cr);
        s_d0t[tslot] = make_float2(cr * norm, sr * norm);

        // D1(K) = e^{i psi}, psi = Om0(src(K)) + Phi1(K), src(K) = K ^ ((K & 0x7F) << 1)
        int src = I ^ ((I & 0x7F) << 1);
        float a1 = 0.0f;
        #pragma unroll
        for (int q = 0; q < 8; q++) {
            float om0  = theta[q * 3 + 2];
            float phi1 = theta[24 + q * 3 + 0];
            a1 += ((src >> q) & 1) ? 0.5f * om0  : -0.5f * om0;
            a1 += ((I   >> q) & 1) ? 0.5f * phi1 : -0.5f * phi1;
        }
        sincosf(a1, &sr, &cr);
        s_d1t[tslot] = make_float2(cr, sr);
        // RZ(om) of layer 1 dropped: no effect on probabilities.
    }
    __syncthreads();

    // ---- main simulation (R10 structure, tables from smem) ----
    int gw   = (int)((blockIdx.x * blockDim.x + tid) >> 5);
    int lane = tid & 31;
    int g    = lane & 15;          // lane-qubit bits (qubits 4..7)
    int base = lane & 16;          // sample selector
    int sample = gw * 2 + (lane >> 4);
    if (gw * 2 >= batch) return;
    int sidx = sample < batch ? sample : batch - 1;

    // ---- angle encoding ----
    float xv = x[sidx * 8 + (g & 7)];
    xv = fminf(1.0f, fmaxf(-1.0f, xv));
    float sv, cv;
    sincospif(0.5f * xv, &sv, &cv);

    float cq[8], sq[8];
    #pragma unroll
    for (int q = 0; q < 8; q++) {
        cq[q] = __shfl_sync(FULL, cv, base | q);
        sq[q] = __shfl_sync(FULL, sv, base | q);
    }
    // lane factor over qubits 4..7 (g bits 0..3)
    float lf = ((g & 1) ? sq[4] : cq[4]) * ((g & 2) ? sq[5] : cq[5])
             * ((g & 4) ? sq[6] : cq[6]) * ((g & 8) ? sq[7] : cq[7]);

    // real product over reg qubits 0..3
    float a0v = lf * cq[0], a1v = lf * sq[0];
    float t2[4], t3[8], amp[16];
    #pragma unroll
    for (int j = 0; j < 4; j++)
        t2[j] = ((j & 1) ? a1v : a0v) * ((j & 2) ? sq[1] : cq[1]);
    #pragma unroll
    for (int j = 0; j < 8; j++)
        t3[j] = t2[j & 3] * ((j & 4) ? sq[2] : cq[2]);
    #pragma unroll
    for (int j = 0; j < 16; j++)
        amp[j] = t3[j & 7] * ((j & 8) ? sq[3] : cq[3]);

    // apply norm-scaled D0 (phi-diagonal of layer 0) -- conflict-free LDS
    const float2* d0p = s_d0t + g;
    float ar[16], ai[16];
    #pragma unroll
    for (int j = 0; j < 16; j++) {
        float2 d = d0p[j * 16];
        ar[j] = amp[j] * d.x;
        ai[j] = amp[j] * d.y;
    }

    // CNOT perm: src lane (4-bit) = g ^ ((g&7)<<1), xor'd with dst reg bit 3
    const int slA = base | (g ^ ((g & 7) << 1));
    const float2* d1p = s_d1t + g;

    // ---- two layers of tangent-form RY gates + fused perm/diagonal ----
    #pragma unroll
    for (int layer = 0; layer < 2; layer++) {
        #pragma unroll
        for (int q = 0; q < 4; q++) {           // reg-qubit gates: 1 FMA/element
            float tg = s_ryt[layer * 8 + q];
            int m = 1 << q;
            #pragma unroll
            for (int j0 = 0; j0 < 16; j0++) {
                if (j0 & m) continue;
                int j1 = j0 | m;
                float b0r = ar[j0], b0i = ai[j0];
                float b1r = ar[j1], b1i = ai[j1];
                ar[j0] = fmaf(-tg, b1r, b0r);
                ai[j0] = fmaf(-tg, b1i, b0i);
                ar[j1] = fmaf( tg, b0r, b1r);
                ai[j1] = fmaf( tg, b0i, b1i);
            }
        }
        #pragma unroll
        for (int q = 4; q < 8; q++) {           // lane-qubit gates: 1 FMA/element
            float tg = s_ryt[layer * 8 + q];
            int pb = 1 << (q - 4);
            float ss = (g & pb) ? tg : -tg;
            #pragma unroll
            for (int j = 0; j < 16; j++) {
                float pr = __shfl_xor_sync(FULL, ar[j], pb);
                float pi = __shfl_xor_sync(FULL, ai[j], pb);
                ar[j] = fmaf(ss, pr, ar[j]);
                ai[j] = fmaf(ss, pi, ai[j]);
            }
        }

        if (layer == 0) {
            // CNOT chain: new[I] = D1[I]*old[src(I)], src = I^((I&0x7F)<<1).
            // Reg part sigma(j)=j^((j&7)<<1): cycles (0)(8)(4 12)(1 3 5 15)(2 6 10 14)(7 9 11 13)
            PERM_STEP(0, 0)
            PERM_STEP(8, 8)
            { float tr_ = ar[4], ti_ = ai[4];
              PERM_STEP(4, 12) PERM_LAST(12) }
            { float tr_ = ar[1], ti_ = ai[1];
              PERM_STEP(1, 3) PERM_STEP(3, 5) PERM_STEP(5, 15) PERM_LAST(15) }
            { float tr_ = ar[2], ti_ = ai[2];
              PERM_STEP(2, 6) PERM_STEP(6, 10) PERM_STEP(10, 14) PERM_LAST(14) }
            { float tr_ = ar[7], ti_ = ai[7];
              PERM_STEP(7, 9) PERM_STEP(9, 11) PERM_STEP(11, 13) PERM_LAST(13) }
        }
        // layer 1: om-diag dropped; its CNOT chain folded into Walsh below.
    }

    // ---- measurement: e_q = sum_I (-1)^{parity(I & (2^{q+1}-1))} p_I ----
    float p[16];
    #pragma unroll
    for (int j = 0; j < 16; j++)
        p[j] = ar[j] * ar[j] + ai[j] * ai[j];

    // signed prefix-parity cascade over reg bits 0..3
    float cA[8], cB[4], cC[2];
    #pragma unroll
    for (int k = 0; k < 8; k++) cA[k] = p[2 * k] - p[2 * k + 1];
    #pragma unroll
    for (int k = 0; k < 4; k++) cB[k] = cA[2 * k] - cA[2 * k + 1];
    cC[0] = cB[0] - cB[1]; cC[1] = cB[2] - cB[3];
    float u0 = 0.0f, u1 = 0.0f;
    #pragma unroll
    for (int k = 0; k < 8; k++) u0 += cA[k];
    #pragma unroll
    for (int k = 0; k < 4; k++) u1 += cB[k];
    float u2 = cC[0] + cC[1];
    float t  = cC[0] - cC[1];     // full reg-parity term, seeds e3..e7

    // butterflies over g bits (within 16-lane sample group):
    // plain sums for u0..u2 (e0..e2); Walsh for t (e3..e7 at g=0,1,3,7,15)
    #pragma unroll
    for (int d = 1; d < 16; d <<= 1) {
        u0 += __shfl_xor_sync(FULL, u0, d);
        u1 += __shfl_xor_sync(FULL, u1, d);
        u2 += __shfl_xor_sync(FULL, u2, d);
        float pv = __shfl_xor_sync(FULL, t, d);
        t = (g & d) ? (pv - t) : (t + pv);
    }

    if (sample < batch) {
        float* o = out + sample * 8;
        if (g == 0) { o[0] = u0; o[1] = u1; o[2] = u2; o[3] = t; }
        else if ((g & (g + 1)) == 0)     // g = 1,3,7,15 -> qubits 4,5,6,7
            o[3 + __popc(g)] = t;
    }
}

extern "C" void kernel_launch(void* const* d_in, const int* in_sizes, int n_in,
                              void* d_out, int out_size) {
    const float* inputs = (const float*)d_in[0];   // [16384, 8] f32
    const float* theta  = (const float*)d_in[1];   // [2, 8, 3]  f32
    float* out = (float*)d_out;                    // [16384, 8] f32

    int batch = in_sizes[0] / 8;

    int warps = (batch + 1) / 2;              // 2 samples per warp
    int threads = 256;                        // 8 warps / block
    int blocks = (warps * 32 + threads - 1) / threads;
    qsim_kernel<<<blocks, threads>>>(inputs, theta, out, batch);
}

// round 13
// speedup vs baseline: 1.1094x; 1.0231x over previous
#include <cuda_runtime.h>

#define FULL 0xffffffffu
#define PI_OVER_2 1.5707963267948966f

// In-place CNOT-perm step fused with D1: new[DST] = D1[DST] * old[SRC]@srclane
#define PERM_STEP(DST, SRC) { \
    int sl_ = slA ^ (((DST) >> 3) & 1); \
    float pr_ = __shfl_sync(FULL, ar[SRC], sl_); \
    float pi_ = __shfl_sync(FULL, ai[SRC], sl_); \
    float2 d_ = d1p[(DST) * 16]; \
    ar[DST] = d_.x * pr_ - d_.y * pi_; \
    ai[DST] = d_.x * pi_ + d_.y * pr_; }

#define PERM_LAST(DST) { \
    int sl_ = slA ^ (((DST) >> 3) & 1); \
    float pr_ = __shfl_sync(FULL, tr_, sl_); \
    float pi_ = __shfl_sync(FULL, ti_, sl_); \
    float2 d_ = d1p[(DST) * 16]; \
    ar[DST] = d_.x * pr_ - d_.y * pi_; \
    ai[DST] = d_.x * pi_ + d_.y * pr_; }

__global__ void __launch_bounds__(256)
qsim_kernel(const float* __restrict__ x, const float* __restrict__ theta,
            float* __restrict__ out, int batch) {
    // ---- per-block theta-derived tables in shared memory (MUFU-fast build) ----
    // Amp index I: bit q = qubit q. qsim layout: I = (g<<4)|j,
    // g = lane&15 (qubits 4..7), j = reg idx (qubits 0..3).
    // Tables transposed [j*16+g] -> conflict-free LDS.
    // Tangent-form gates: s_ryt[k] = tan(th_k/2); product of all 16 cos(th_k/2)
    // is folded into s_d0t, so each gate costs 1 FMA/element.
    // All angles are small (|th|/2 ~ 0.05, |psi| < ~3), safely inside MUFU range.
    __shared__ float  s_ryt[16];
    __shared__ float  s_ryc[16];
    __shared__ __align__(16) float2 s_d0t[256];   // norm * (cos phi, sin phi)
    __shared__ __align__(16) float2 s_d1t[256];   // (cos psi, sin psi)

    int tid = threadIdx.x;
    if (tid < 16) {
        int layer = tid >> 3, q = tid & 7;
        float th = 0.5f * theta[layer * 24 + q * 3 + 1];
        float sg, cg;
        __sincosf(th, &sg, &cg);
        s_ryt[tid] = __fdividef(sg, cg);
        s_ryc[tid] = cg;
    }
    __syncthreads();

    {
        int I = tid;                           // amp index 0..255
        float norm = 1.0f;
        #pragma unroll
        for (int k = 0; k < 16; k++) norm *= s_ryc[k];

        int tslot = (I & 15) * 16 + (I >> 4);  // transposed slot

        // D0: RZ(phi) layer 0 diag (bit=0 -> -phi/2, bit=1 -> +phi/2), scaled by norm
        float a0 = 0.0f;
        #pragma unroll
        for (int q = 0; q < 8; q++) {
            float phi = theta[q * 3 + 0];
            a0 += ((I >> q) & 1) ? 0.5f * phi : -0.5f * phi;
        }
        float sr, cr;
        __sincosf(a0, &sr, &cr);
        s_d0t[tslot] = make_float2(cr * norm, sr * norm);

        // D1(K) = e^{i psi}, psi = Om0(src(K)) + Phi1(K), src(K) = K ^ ((K & 0x7F) << 1)
        int src = I ^ ((I & 0x7F) << 1);
        float a1 = 0.0f;
        #pragma unroll
        for (int q = 0; q < 8; q++) {
            float om0  = theta[q * 3 + 2];
            float phi1 = theta[24 + q * 3 + 0];
            a1 += ((src >> q) & 1) ? 0.5f * om0  : -0.5f * om0;
            a1 += ((I   >> q) & 1) ? 0.5f * phi1 : -0.5f * phi1;
        }
        __sincosf(a1, &sr, &cr);
        s_d1t[tslot] = make_float2(cr, sr);
        // RZ(om) of layer 1 dropped: no effect on probabilities.
    }
    __syncthreads();

    // ---- main simulation (R10 structure, tables from smem) ----
    int gw   = (int)((blockIdx.x * blockDim.x + tid) >> 5);
    int lane = tid & 31;
    int g    = lane & 15;          // lane-qubit bits (qubits 4..7)
    int base = lane & 16;          // sample selector
    int sample = gw * 2 + (lane >> 4);
    if (gw * 2 >= batch) return;
    int sidx = sample < batch ? sample : batch - 1;

    // ---- angle encoding (MUFU sin/cos of (pi/2)*x, x clipped to [-1,1]) ----
    float xv = x[sidx * 8 + (g & 7)];
    xv = fminf(1.0f, fmaxf(-1.0f, xv));
    float sv, cv;
    __sincosf(PI_OVER_2 * xv, &sv, &cv);

    float cq[8], sq[8];
    #pragma unroll
    for (int q = 0; q < 8; q++) {
        cq[q] = __shfl_sync(FULL, cv, base | q);
        sq[q] = __shfl_sync(FULL, sv, base | q);
    }
    // lane factor over qubits 4..7 (g bits 0..3)
    float lf = ((g & 1) ? sq[4] : cq[4]) * ((g & 2) ? sq[5] : cq[5])
             * ((g & 4) ? sq[6] : cq[6]) * ((g & 8) ? sq[7] : cq[7]);

    // real product over reg qubits 0..3
    float a0v = lf * cq[0], a1v = lf * sq[0];
    float t2[4], t3[8], amp[16];
    #pragma unroll
    for (int j = 0; j < 4; j++)
        t2[j] = ((j & 1) ? a1v : a0v) * ((j & 2) ? sq[1] : cq[1]);
    #pragma unroll
    for (int j = 0; j < 8; j++)
        t3[j] = t2[j & 3] * ((j & 4) ? sq[2] : cq[2]);
    #pragma unroll
    for (int j = 0; j < 16; j++)
        amp[j] = t3[j & 7] * ((j & 8) ? sq[3] : cq[3]);

    // apply norm-scaled D0 (phi-diagonal of layer 0) -- conflict-free LDS
    const float2* d0p = s_d0t + g;
    float ar[16], ai[16];
    #pragma unroll
    for (int j = 0; j < 16; j++) {
        float2 d = d0p[j * 16];
        ar[j] = amp[j] * d.x;
        ai[j] = amp[j] * d.y;
    }

    // CNOT perm: src lane (4-bit) = g ^ ((g&7)<<1), xor'd with dst reg bit 3
    const int slA = base | (g ^ ((g & 7) << 1));
    const float2* d1p = s_d1t + g;

    // ---- two layers of tangent-form RY gates + fused perm/diagonal ----
    #pragma unroll
    for (int layer = 0; layer < 2; layer++) {
        #pragma unroll
        for (int q = 0; q < 4; q++) {           // reg-qubit gates: 1 FMA/element
            float tg = s_ryt[layer * 8 + q];
            int m = 1 << q;
            #pragma unroll
            for (int j0 = 0; j0 < 16; j0++) {
                if (j0 & m) continue;
                int j1 = j0 | m;
                float b0r = ar[j0], b0i = ai[j0];
                float b1r = ar[j1], b1i = ai[j1];
                ar[j0] = fmaf(-tg, b1r, b0r);
                ai[j0] = fmaf(-tg, b1i, b0i);
                ar[j1] = fmaf( tg, b0r, b1r);
                ai[j1] = fmaf( tg, b0i, b1i);
            }
        }
        #pragma unroll
        for (int q = 4; q < 8; q++) {           // lane-qubit gates: 1 FMA/element
            float tg = s_ryt[layer * 8 + q];
            int pb = 1 << (q - 4);
            float ss = (g & pb) ? tg : -tg;
            #pragma unroll
            for (int j = 0; j < 16; j++) {
                float pr = __shfl_xor_sync(FULL, ar[j], pb);
                float pi = __shfl_xor_sync(FULL, ai[j], pb);
                ar[j] = fmaf(ss, pr, ar[j]);
                ai[j] = fmaf(ss, pi, ai[j]);
            }
        }

        if (layer == 0) {
            // CNOT chain: new[I] = D1[I]*old[src(I)], src = I^((I&0x7F)<<1).
            // Reg part sigma(j)=j^((j&7)<<1): cycles (0)(8)(4 12)(1 3 5 15)(2 6 10 14)(7 9 11 13)
            PERM_STEP(0, 0)
            PERM_STEP(8, 8)
            { float tr_ = ar[4], ti_ = ai[4];
              PERM_STEP(4, 12) PERM_LAST(12) }
            { float tr_ = ar[1], ti_ = ai[1];
              PERM_STEP(1, 3) PERM_STEP(3, 5) PERM_STEP(5, 15) PERM_LAST(15) }
            { float tr_ = ar[2], ti_ = ai[2];
              PERM_STEP(2, 6) PERM_STEP(6, 10) PERM_STEP(10, 14) PERM_LAST(14) }
            { float tr_ = ar[7], ti_ = ai[7];
              PERM_STEP(7, 9) PERM_STEP(9, 11) PERM_STEP(11, 13) PERM_LAST(13) }
        }
        // layer 1: om-diag dropped; its CNOT chain folded into Walsh below.
    }

    // ---- measurement: e_q = sum_I (-1)^{parity(I & (2^{q+1}-1))} p_I ----
    float p[16];
    #pragma unroll
    for (int j = 0; j < 16; j++)
        p[j] = ar[j] * ar[j] + ai[j] * ai[j];

    // signed prefix-parity cascade over reg bits 0..3
    float cA[8], cB[4], cC[2];
    #pragma unroll
    for (int k = 0; k < 8; k++) cA[k] = p[2 * k] - p[2 * k + 1];
    #pragma unroll
    for (int k = 0; k < 4; k++) cB[k] = cA[2 * k] - cA[2 * k + 1];
    cC[0] = cB[0] - cB[1]; cC[1] = cB[2] - cB[3];
    float u0 = 0.0f, u1 = 0.0f;
    #pragma unroll
    for (int k = 0; k < 8; k++) u0 += cA[k];
    #pragma unroll
    for (int k = 0; k < 4; k++) u1 += cB[k];
    float u2 = cC[0] + cC[1];
    float t  = cC[0] - cC[1];     // full reg-parity term, seeds e3..e7

    // butterflies over g bits (within 16-lane sample group):
    // plain sums for u0..u2 (e0..e2); Walsh for t (e3..e7 at g=0,1,3,7,15)
    #pragma unroll
    for (int d = 1; d < 16; d <<= 1) {
        u0 += __shfl_xor_sync(FULL, u0, d);
        u1 += __shfl_xor_sync(FULL, u1, d);
        u2 += __shfl_xor_sync(FULL, u2, d);
        float pv = __shfl_xor_sync(FULL, t, d);
        t = (g & d) ? (pv - t) : (t + pv);
    }

    if (sample < batch) {
        float* o = out + sample * 8;
        if (g == 0) { o[0] = u0; o[1] = u1; o[2] = u2; o[3] = t; }
        else if ((g & (g + 1)) == 0)     // g = 1,3,7,15 -> qubits 4,5,6,7
            o[3 + __popc(g)] = t;
    }
}

extern "C" void kernel_launch(void* const* d_in, const int* in_sizes, int n_in,
                              void* d_out, int out_size) {
    const float* inputs = (const float*)d_in[0];   // [16384, 8] f32
    const float* theta  = (const float*)d_in[1];   // [2, 8, 3]  f32
    float* out = (float*)d_out;                    // [16384, 8] f32

    int batch = in_sizes[0] / 8;

    int warps = (batch + 1) / 2;              // 2 samples per warp
    int threads = 256;                        // 8 warps / block
    int blocks = (warps * 32 + threads - 1) / threads;
    qsim_kernel<<<blocks, threads>>>(inputs, theta, out, batch);
}